// round 15
// baseline (speedup 1.0000x reference)
#include <cuda_runtime.h>
#include <math.h>

// LSTM: S=512, B=64, I=H=1024, fp32.
//  Phase 1: gates_x = x @ W_ih^T + b_ih + b_hh  (proven FFMA2 GEMM, R8).
//           Also resets the recurrence flags (stream-ordered before Phase 2).
//  Phase 2: persistent recurrent kernel, NOW 512 threads/CTA (4 warps/SMSP):
//           R4(1 warp/SMSP)=52us/step, R8(2)=33us/step -> latency-exposure
//           scaling; 4 warps/SMSP + LDS.128 predicted ~12us/step.
//
// Output layout: [0,S*B*H) output; then h_last [B*H]; then c_last [B*H].

typedef unsigned long long u64;

#define SEQ 512
#define BATCH 64
#define HID 1024
#define G4 4096
#define BH (BATCH * HID)
#define NCTA 128

// scratch (allocation-free rule: __device__ globals)
__device__ float g_gx[(size_t)SEQ * BATCH * G4];     // precomputed input gates
__device__ volatile unsigned int g_arrive[NCTA];     // per-CTA step flags

static __device__ __forceinline__ void ffma2(u64 &d, u64 a, u64 b) {
    asm volatile("fma.rn.f32x2 %0, %1, %2, %0;" : "+l"(d) : "l"(a), "l"(b));
}
static __device__ __forceinline__ u64 pack2(float x, float y) {
    u64 r; asm("mov.b64 %0, {%1, %2};" : "=l"(r) : "f"(x), "f"(y)); return r;
}
static __device__ __forceinline__ float hadd2(u64 v) {
    float x, y; asm("mov.b64 {%0, %1}, %2;" : "=f"(x), "=f"(y) : "l"(v));
    return x + y;
}

// ---------------------------------------------------------------------------
// Phase 1 GEMM: C[m][n] = sum_k X[m][k] * Wih[n][k] + (bih[n] + bhh[n])
// M=32768, N=4096, K=1024. BM=BN=128, BK=16, 512 threads, 8m x 4n per thread.
// (proven R8 version; CTA(0,0) additionally resets the recurrence flags)
// ---------------------------------------------------------------------------
__global__ __launch_bounds__(512, 1)
void gemm_gates_x(const float* __restrict__ X, const float* __restrict__ W,
                  const float* __restrict__ bih, const float* __restrict__ bhh)
{
    __shared__ u64 As[2][8][129];
    __shared__ u64 Bs[2][8][129];

    const int t  = threadIdx.x;
    const int n0 = blockIdx.x * 128;
    const int m0 = blockIdx.y * 128;

    if (blockIdx.x == 0 && blockIdx.y == 0 && t < NCTA) g_arrive[t] = 0u;

    const int lrow = t >> 2;
    const int lq   = t & 3;
    const float* ap = X + (size_t)(m0 + lrow) * 1024 + lq * 4;
    const float* bp = W + (size_t)(n0 + lrow) * 1024 + lq * 4;

    const int tn = t & 31;
    const int tm = t >> 5;

    u64 acc[8][4];
#pragma unroll
    for (int i = 0; i < 8; i++)
#pragma unroll
        for (int jj = 0; jj < 4; jj++) acc[i][jj] = 0ull;

    float4 av = *(const float4*)ap;
    float4 bv = *(const float4*)bp;
    As[0][lq * 2][lrow]     = pack2(av.x, av.y);
    As[0][lq * 2 + 1][lrow] = pack2(av.z, av.w);
    Bs[0][lq * 2][lrow]     = pack2(bv.x, bv.y);
    Bs[0][lq * 2 + 1][lrow] = pack2(bv.z, bv.w);
    __syncthreads();

    int buf = 0;
    for (int kt = 0; kt < 64; kt++) {
        if (kt < 63) {
            av = *(const float4*)(ap + (kt + 1) * 16);
            bv = *(const float4*)(bp + (kt + 1) * 16);
        }
#pragma unroll
        for (int q = 0; q < 8; q++) {
            u64 a8[8], b4[4];
#pragma unroll
            for (int i = 0; i < 8; i++) a8[i] = As[buf][q][tm * 8 + i];
#pragma unroll
            for (int jj = 0; jj < 4; jj++) b4[jj] = Bs[buf][q][tn + 32 * jj];
#pragma unroll
            for (int i = 0; i < 8; i++)
#pragma unroll
                for (int jj = 0; jj < 4; jj++) ffma2(acc[i][jj], a8[i], b4[jj]);
        }
        if (kt < 63) {
            As[buf ^ 1][lq * 2][lrow]     = pack2(av.x, av.y);
            As[buf ^ 1][lq * 2 + 1][lrow] = pack2(av.z, av.w);
            Bs[buf ^ 1][lq * 2][lrow]     = pack2(bv.x, bv.y);
            Bs[buf ^ 1][lq * 2 + 1][lrow] = pack2(bv.z, bv.w);
            __syncthreads();
            buf ^= 1;
        }
    }

#pragma unroll
    for (int jj = 0; jj < 4; jj++) {
        const int n = n0 + tn + 32 * jj;
        const float bias = bih[n] + bhh[n];
#pragma unroll
        for (int i = 0; i < 8; i++) {
            const int m = m0 + tm * 8 + i;
            g_gx[(size_t)m * G4 + n] = hadd2(acc[i][jj]) + bias;
        }
    }
}

// ---------------------------------------------------------------------------
// Phase 2: persistent recurrent kernel, 512 threads (4 warps/SMSP).
// 128 CTAs; CTA owns 8 hidden cols x 4 gates = 32 W_hh rows, resident in SMEM
// for all 512 steps. Thread: j = tid&7, b = tid>>3 (one batch), 4 gates ->
// 4 packed f32x2 accumulators + 1 register-resident cell state.
// SMEM: ws[32][514] u64 (131,584B) + hs[64][130] u64 (66,560B) = 198,144B.
//   Even strides keep ulonglong2 16B-aligned. Banks (u64-pairs mod 16):
//   W rows j*514 = 2j -> 8 distinct; h rows b*130 = 2b -> 4 distinct within a
//   warp's 4 batches. Both LDS.128 patterns conflict-free.
// Lock-step distributed flag barrier (proven R8): tid<128 poll distinct slots.
// ---------------------------------------------------------------------------
#define WS_STRIDE 514
#define HS_STRIDE 130
#define WS_U64 (32 * WS_STRIDE)
#define STEP_SMEM ((WS_U64 + 64 * HS_STRIDE) * 8)   // 198,144 B

__global__ __launch_bounds__(512, 1)
void lstm_persist(const float* __restrict__ h0, const float* __restrict__ c0,
                  const float* __restrict__ Whh, float* __restrict__ out)
{
    extern __shared__ u64 sm[];
    u64 (*ws)[WS_STRIDE] = (u64(*)[WS_STRIDE])sm;       // [32 W rows][512 kp]
    u64 (*hs)[HS_STRIDE] = (u64(*)[HS_STRIDE])(sm + WS_U64); // [64 b][128 kp]

    const int tid = threadIdx.x;
    const int j   = tid & 7;
    const int b   = tid >> 3;            // 0..63, one batch per thread
    const int j0  = blockIdx.x * 8;
    const int col = j0 + j;

    // ---- load this CTA's 32 W_hh rows into SMEM once ----
    for (int idx = tid; idx < 8192; idx += 512) {       // 8192 float4
        const int r  = idx >> 8;
        const int c4 = idx & 255;
        const int grow = (r >> 3) * 1024 + j0 + (r & 7);
        float4 v = *(const float4*)(Whh + (size_t)grow * 1024 + c4 * 4);
        ws[r][c4 * 2]     = pack2(v.x, v.y);
        ws[r][c4 * 2 + 1] = pack2(v.z, v.w);
    }

    // per-thread W row pointers (4 gates)
    const u64* wr0 = &ws[0 * 8 + j][0];
    const u64* wr1 = &ws[1 * 8 + j][0];
    const u64* wr2 = &ws[2 * 8 + j][0];
    const u64* wr3 = &ws[3 * 8 + j][0];
    const u64* hp  = &hs[b][0];

    // ---- cell state lives in a register for the whole run ----
    float creg = c0[b * HID + col];
    __syncthreads();

    for (int t = 0; t < SEQ; t++) {
        // prefetch this step's input-gate values (static data)
        float gx[4];
#pragma unroll
        for (int g = 0; g < 4; g++)
            gx[g] = g_gx[((size_t)t * BATCH + b) * G4 + g * 1024 + col];

        // acquire: tid<128 poll distinct per-CTA flags (no atomic traffic)
        if (t > 0) {
            if (tid < NCTA) {
                while (g_arrive[tid] < (unsigned)t) { __nanosleep(20); }
            }
            __threadfence();
            __syncthreads();
        }

        const float* h_in = (t == 0) ? h0 : (out + (size_t)(t - 1) * BH);

        u64 acc[4];
        acc[0] = acc[1] = acc[2] = acc[3] = 0ull;

        for (int ck = 0; ck < 4; ck++) {
            const int kbase = ck * 256;
            // stage h chunk: 64 rows x 256 floats (coalesced float4, __ldcg)
            for (int idx = tid; idx < 4096; idx += 512) {
                const int r = idx >> 6, c4 = idx & 63;
                float4 v = __ldcg((const float4*)(h_in + r * 1024 + kbase + c4 * 4));
                hs[r][c4 * 2]     = pack2(v.x, v.y);
                hs[r][c4 * 2 + 1] = pack2(v.z, v.w);
            }
            __syncthreads();

            const int gk0 = ck * 128;
#pragma unroll 4
            for (int k2 = 0; k2 < 64; k2++) {
                ulonglong2 w0 = *(const ulonglong2*)(wr0 + gk0 + 2 * k2);
                ulonglong2 w1 = *(const ulonglong2*)(wr1 + gk0 + 2 * k2);
                ulonglong2 w2 = *(const ulonglong2*)(wr2 + gk0 + 2 * k2);
                ulonglong2 w3 = *(const ulonglong2*)(wr3 + gk0 + 2 * k2);
                ulonglong2 hv = *(const ulonglong2*)(hp + 2 * k2);
                ffma2(acc[0], w0.x, hv.x);
                ffma2(acc[1], w1.x, hv.x);
                ffma2(acc[2], w2.x, hv.x);
                ffma2(acc[3], w3.x, hv.x);
                ffma2(acc[0], w0.y, hv.y);
                ffma2(acc[1], w1.y, hv.y);
                ffma2(acc[2], w2.y, hv.y);
                ffma2(acc[3], w3.y, hv.y);
            }
            __syncthreads();
        }

        // ---- fused cell update (c in register, h -> global) ----
        {
            const float gi = hadd2(acc[0]) + gx[0];
            const float gf = hadd2(acc[1]) + gx[1];
            const float gg = hadd2(acc[2]) + gx[2];
            const float go = hadd2(acc[3]) + gx[3];

            const float ig = 1.0f / (1.0f + expf(-gi));
            const float fg = 1.0f / (1.0f + expf(-gf));
            const float gt = tanhf(gg);
            const float og = 1.0f / (1.0f + expf(-go));

            const float cn = fg * creg + ig * gt;
            const float hn = og * tanhf(cn);
            creg = cn;

            out[(size_t)t * BH + b * HID + col] = hn;
            if (t == SEQ - 1) {
                out[(size_t)SEQ * BH + b * HID + col] = hn;        // h_last
                out[(size_t)SEQ * BH + BH + b * HID + col] = cn;   // c_last
            }
        }

        // ---- release: publish h[t] ----
        if (t < SEQ - 1) {
            __threadfence();
            __syncthreads();
            if (tid == 0) g_arrive[blockIdx.x] = (unsigned)(t + 1);
        }
    }
}

extern "C" void kernel_launch(void* const* d_in, const int* in_sizes, int n_in,
                              void* d_out, int out_size)
{
    const float* x    = (const float*)d_in[0];
    const float* h0   = (const float*)d_in[1];
    const float* c0   = (const float*)d_in[2];
    const float* Wih  = (const float*)d_in[3];
    const float* bih  = (const float*)d_in[4];
    const float* Whh  = (const float*)d_in[5];
    const float* bhh  = (const float*)d_in[6];
    float* out = (float*)d_out;

    cudaFuncSetAttribute(lstm_persist,
                         cudaFuncAttributeMaxDynamicSharedMemorySize, STEP_SMEM);

    gemm_gates_x<<<dim3(32, 256), 512>>>(x, Wih, bih, bhh);
    lstm_persist<<<NCTA, 512, STEP_SMEM>>>(h0, c0, Whh, out);
}

// round 16
// speedup vs baseline: 1.6255x; 1.6255x over previous
#include <cuda_runtime.h>
#include <math.h>

// LSTM: S=512, B=64, I=H=1024, fp32.
//  Phase 1: gates_x = x @ W_ih^T + b_ih + b_hh  (proven FFMA2 GEMM; also
//           resets the recurrence flags, stream-ordered before Phase 2).
//  Phase 2: persistent recurrent kernel, 128 CTAs x 256 threads.
//   R16 vs R15: profile showed SMEM-crossbar-bound (L1=74%, fma=16%), with
//   cost = per-lane bytes (no broadcast dedup). Fix: fat (8 rows x 4 batch)
//   register tile -> crossbar 24.6K cyc/step (vs 82K in R15, 49K in R8).
//   4-way k-split keeps 256 threads; SMEM partial reduction at step end.
//   h staged with per-batch XOR swizzle -> conflict-free strided-batch LDS.128.
//
// Output layout: [0,S*B*H) output; then h_last [B*H]; then c_last [B*H].

typedef unsigned long long u64;

#define SEQ 512
#define BATCH 64
#define HID 1024
#define G4 4096
#define BH (BATCH * HID)
#define NCTA 128

__device__ float g_gx[(size_t)SEQ * BATCH * G4];     // precomputed input gates
__device__ volatile unsigned int g_arrive[NCTA];     // per-CTA step flags

static __device__ __forceinline__ void ffma2(u64 &d, u64 a, u64 b) {
    asm volatile("fma.rn.f32x2 %0, %1, %2, %0;" : "+l"(d) : "l"(a), "l"(b));
}
static __device__ __forceinline__ void fadd2(u64 &d, u64 a) {
    asm volatile("add.rn.f32x2 %0, %0, %1;" : "+l"(d) : "l"(a));
}
static __device__ __forceinline__ u64 pack2(float x, float y) {
    u64 r; asm("mov.b64 %0, {%1, %2};" : "=l"(r) : "f"(x), "f"(y)); return r;
}
static __device__ __forceinline__ float hadd2(u64 v) {
    float x, y; asm("mov.b64 {%0, %1}, %2;" : "=f"(x), "=f"(y) : "l"(v));
    return x + y;
}

// ---------------------------------------------------------------------------
// Phase 1 GEMM (unchanged, proven): C = X @ W^T + bias. BM=BN=128, BK=16.
// ---------------------------------------------------------------------------
__global__ __launch_bounds__(512, 1)
void gemm_gates_x(const float* __restrict__ X, const float* __restrict__ W,
                  const float* __restrict__ bih, const float* __restrict__ bhh)
{
    __shared__ u64 As[2][8][129];
    __shared__ u64 Bs[2][8][129];

    const int t  = threadIdx.x;
    const int n0 = blockIdx.x * 128;
    const int m0 = blockIdx.y * 128;

    if (blockIdx.x == 0 && blockIdx.y == 0 && t < NCTA) g_arrive[t] = 0u;

    const int lrow = t >> 2;
    const int lq   = t & 3;
    const float* ap = X + (size_t)(m0 + lrow) * 1024 + lq * 4;
    const float* bp = W + (size_t)(n0 + lrow) * 1024 + lq * 4;

    const int tn = t & 31;
    const int tm = t >> 5;

    u64 acc[8][4];
#pragma unroll
    for (int i = 0; i < 8; i++)
#pragma unroll
        for (int jj = 0; jj < 4; jj++) acc[i][jj] = 0ull;

    float4 av = *(const float4*)ap;
    float4 bv = *(const float4*)bp;
    As[0][lq * 2][lrow]     = pack2(av.x, av.y);
    As[0][lq * 2 + 1][lrow] = pack2(av.z, av.w);
    Bs[0][lq * 2][lrow]     = pack2(bv.x, bv.y);
    Bs[0][lq * 2 + 1][lrow] = pack2(bv.z, bv.w);
    __syncthreads();

    int buf = 0;
    for (int kt = 0; kt < 64; kt++) {
        if (kt < 63) {
            av = *(const float4*)(ap + (kt + 1) * 16);
            bv = *(const float4*)(bp + (kt + 1) * 16);
        }
#pragma unroll
        for (int q = 0; q < 8; q++) {
            u64 a8[8], b4[4];
#pragma unroll
            for (int i = 0; i < 8; i++) a8[i] = As[buf][q][tm * 8 + i];
#pragma unroll
            for (int jj = 0; jj < 4; jj++) b4[jj] = Bs[buf][q][tn + 32 * jj];
#pragma unroll
            for (int i = 0; i < 8; i++)
#pragma unroll
                for (int jj = 0; jj < 4; jj++) ffma2(acc[i][jj], a8[i], b4[jj]);
        }
        if (kt < 63) {
            As[buf ^ 1][lq * 2][lrow]     = pack2(av.x, av.y);
            As[buf ^ 1][lq * 2 + 1][lrow] = pack2(av.z, av.w);
            Bs[buf ^ 1][lq * 2][lrow]     = pack2(bv.x, bv.y);
            Bs[buf ^ 1][lq * 2 + 1][lrow] = pack2(bv.z, bv.w);
            __syncthreads();
            buf ^= 1;
        }
    }

#pragma unroll
    for (int jj = 0; jj < 4; jj++) {
        const int n = n0 + tn + 32 * jj;
        const float bias = bih[n] + bhh[n];
#pragma unroll
        for (int i = 0; i < 8; i++) {
            const int m = m0 + tm * 8 + i;
            g_gx[(size_t)m * G4 + n] = hadd2(acc[i][jj]) + bias;
        }
    }
}

// ---------------------------------------------------------------------------
// Phase 2: persistent recurrent kernel, 256 threads, (8 rows x 4 batch) tile.
// Thread (compute role): ks = tid>>6 (k-slice), bq = (tid&63)>>2, jp = tid&3.
//   W rows: g*8 + 2*jp + {0,1} (g<4); batches: bq + 16*i (i<4).
//   32 packed f32x2 accumulators; 12 LDS.128 + 64 FFMA2 per 4-k iteration.
// SMEM: ws[32][514] u64 (131,584B; jp rows -> 16B groups {0,32,64,96}) +
//       hs/red buffer 8,720 u64 (69,760B). Total 201,344B -> 1 CTA/SM.
// h chunk layout (256 k): row b at b*128 u64; 16B-chunk q stored at
//   (q ^ (b&7)) -> strided-batch reads (b = bq+16i, same b&7) conflict-free.
// Step end: partials -> SMEM (cell*17 + g*4 + ks), reduce 4 k-slices,
//   fused cell update by reduction thread (2 cells/thread, c in registers).
// ---------------------------------------------------------------------------
#define WS_STRIDE 514
#define WS_U64 (32 * WS_STRIDE)
#define RED_U64 (512 * 17 + 16)
#define STEP_SMEM ((WS_U64 + RED_U64) * 8)          // 201,344 B

__global__ __launch_bounds__(256, 1)
void lstm_persist(const float* __restrict__ h0, const float* __restrict__ c0,
                  const float* __restrict__ Whh, float* __restrict__ out)
{
    extern __shared__ u64 sm[];
    u64* ws = sm;                        // [32][514]
    u64* hs = sm + WS_U64;               // h chunk [64][128] (also red buffer)

    const int tid = threadIdx.x;
    const int j0  = blockIdx.x * 8;

    // compute role
    const int ks = tid >> 6;             // 0..3 k-slice
    const int bq = (tid & 63) >> 2;      // 0..15
    const int jp = tid & 3;              // 0..3 (j pair)
    const int xb = bq & 7;               // h swizzle constant (same for 4 b's)

    // reduction role: cells 2*tid, 2*tid+1;  cell = b*8 + jo
    const int rc0 = 2 * tid;
    const int rb0 = rc0 >> 3, rj0 = rc0 & 7;
    const int rb1 = (rc0 + 1) >> 3, rj1 = (rc0 + 1) & 7;

    // ---- load this CTA's 32 W_hh rows into SMEM once ----
    for (int idx = tid; idx < 8192; idx += 256) {       // 8192 float4
        const int r  = idx >> 8;
        const int c4 = idx & 255;
        const int grow = (r >> 3) * 1024 + j0 + (r & 7);
        float4 v = *(const float4*)(Whh + (size_t)grow * 1024 + c4 * 4);
        ws[r * WS_STRIDE + c4 * 2]     = pack2(v.x, v.y);
        ws[r * WS_STRIDE + c4 * 2 + 1] = pack2(v.z, v.w);
    }

    // h row base pointers for this thread's 4 batches
    const u64* hrow[4];
#pragma unroll
    for (int i = 0; i < 4; i++) hrow[i] = hs + (size_t)(bq + 16 * i) * 128;

    // ---- cell state in registers (reduction role) ----
    float creg[2];
    creg[0] = c0[rb0 * HID + j0 + rj0];
    creg[1] = c0[rb1 * HID + j0 + rj1];
    __syncthreads();

    for (int t = 0; t < SEQ; t++) {
        // prefetch gx for my 2 cells (static data; overlaps the wait)
        float gx[2][4];
#pragma unroll
        for (int g = 0; g < 4; g++) {
            gx[0][g] = g_gx[((size_t)t * BATCH + rb0) * G4 + g * 1024 + j0 + rj0];
            gx[1][g] = g_gx[((size_t)t * BATCH + rb1) * G4 + g * 1024 + j0 + rj1];
        }

        // acquire: tid<128 poll distinct per-CTA flags
        if (t > 0) {
            if (tid < NCTA) {
                while (g_arrive[tid] < (unsigned)t) { __nanosleep(20); }
            }
            __threadfence();
            __syncthreads();
        }

        const float* h_in = (t == 0) ? h0 : (out + (size_t)(t - 1) * BH);

        u64 acc[4][2][4];                // [gate][jo-half][batch]
#pragma unroll
        for (int g = 0; g < 4; g++)
#pragma unroll
            for (int o = 0; o < 2; o++)
#pragma unroll
                for (int i = 0; i < 4; i++) acc[g][o][i] = 0ull;

        for (int ck = 0; ck < 4; ck++) {
            // stage h chunk: 64 rows x 256 k, swizzled 16B groups
            {
                const int kbase = ck * 256;
                for (int idx = tid; idx < 4096; idx += 256) {
                    const int r = idx >> 6, q = idx & 63;
                    float4 v = __ldcg((const float4*)(h_in + r * 1024 + kbase + q * 4));
                    u64* dst = hs + r * 128 + ((q ^ (r & 7)) * 2);
                    dst[0] = pack2(v.x, v.y);
                    dst[1] = pack2(v.z, v.w);
                }
            }
            __syncthreads();

            const int kwu = ck * 128 + ks * 32;   // ws u64 base for my slice
            const int qb  = ks * 16;              // hs 16B-chunk base
#pragma unroll 4
            for (int it = 0; it < 16; it++) {
                ulonglong2 w[4][2];
#pragma unroll
                for (int g = 0; g < 4; g++)
#pragma unroll
                    for (int o = 0; o < 2; o++)
                        w[g][o] = *(const ulonglong2*)
                            (ws + (g * 8 + 2 * jp + o) * WS_STRIDE + kwu + it * 2);
                const int sq = ((qb + it) ^ xb) * 2;
                ulonglong2 hv[4];
#pragma unroll
                for (int i = 0; i < 4; i++)
                    hv[i] = *(const ulonglong2*)(hrow[i] + sq);
#pragma unroll
                for (int g = 0; g < 4; g++)
#pragma unroll
                    for (int o = 0; o < 2; o++)
#pragma unroll
                        for (int i = 0; i < 4; i++) {
                            ffma2(acc[g][o][i], w[g][o].x, hv[i].x);
                            ffma2(acc[g][o][i], w[g][o].y, hv[i].y);
                        }
            }
            __syncthreads();
        }

        // ---- store partials: red[cell*17 + g*4 + ks], cell = b*8 + jo ----
        u64* red = hs;
#pragma unroll
        for (int g = 0; g < 4; g++)
#pragma unroll
            for (int o = 0; o < 2; o++)
#pragma unroll
                for (int i = 0; i < 4; i++) {
                    const int cell = (bq + 16 * i) * 8 + (2 * jp + o);
                    red[cell * 17 + g * 4 + ks] = acc[g][o][i];
                }
        __syncthreads();

        // ---- reduce 4 k-slices + fused cell update (2 cells/thread) ----
#pragma unroll
        for (int ci = 0; ci < 2; ci++) {
            const int cell = rc0 + ci;
            const int b = (ci == 0) ? rb0 : rb1;
            const int jo = (ci == 0) ? rj0 : rj1;
            const u64* rp = red + cell * 17;
            float gv[4];
#pragma unroll
            for (int g = 0; g < 4; g++) {
                u64 s = rp[g * 4 + 0];
                fadd2(s, rp[g * 4 + 1]);
                fadd2(s, rp[g * 4 + 2]);
                fadd2(s, rp[g * 4 + 3]);
                gv[g] = hadd2(s) + gx[ci][g];
            }
            const float ig = 1.0f / (1.0f + expf(-gv[0]));
            const float fg = 1.0f / (1.0f + expf(-gv[1]));
            const float gt = tanhf(gv[2]);
            const float og = 1.0f / (1.0f + expf(-gv[3]));

            const float cn = fg * creg[ci] + ig * gt;
            const float hn = og * tanhf(cn);
            creg[ci] = cn;

            out[(size_t)t * BH + b * HID + j0 + jo] = hn;
            if (t == SEQ - 1) {
                out[(size_t)SEQ * BH + b * HID + j0 + jo] = hn;       // h_last
                out[(size_t)SEQ * BH + BH + b * HID + j0 + jo] = cn;  // c_last
            }
        }

        // ---- release: publish h[t] ----
        if (t < SEQ - 1) {
            __threadfence();
            __syncthreads();
            if (tid == 0) g_arrive[blockIdx.x] = (unsigned)(t + 1);
        }
    }
}

extern "C" void kernel_launch(void* const* d_in, const int* in_sizes, int n_in,
                              void* d_out, int out_size)
{
    const float* x    = (const float*)d_in[0];
    const float* h0   = (const float*)d_in[1];
    const float* c0   = (const float*)d_in[2];
    const float* Wih  = (const float*)d_in[3];
    const float* bih  = (const float*)d_in[4];
    const float* Whh  = (const float*)d_in[5];
    const float* bhh  = (const float*)d_in[6];
    float* out = (float*)d_out;

    cudaFuncSetAttribute(lstm_persist,
                         cudaFuncAttributeMaxDynamicSharedMemorySize, STEP_SMEM);

    gemm_gates_x<<<dim3(32, 256), 512>>>(x, Wih, bih, bhh);
    lstm_persist<<<NCTA, 256, STEP_SMEM>>>(h0, c0, Whh, out);
}